// round 1
// baseline (speedup 1.0000x reference)
#include <cuda_runtime.h>
#include <math.h>

#define BATCH 2048
#define SEQ   64
#define DIN   512
#define HID   1024
#define CIN   (DIN + HID)

#define BM  64
#define BN  64
#define BK  16
#define PAD 68   // 16B-aligned row pitch, breaks the 4-way store bank conflict

// ping-pong hidden-state buffers (8 MB each) — device globals, no allocation
__device__ float g_hbuf[2][BATCH * HID];

__global__ __launch_bounds__(256)
void lnn_step(const float* __restrict__ x,
              const float* __restrict__ Wf, const float* __restrict__ bf,
              const float* __restrict__ Wg, const float* __restrict__ bg,
              const float* __restrict__ Wh, const float* __restrict__ bh,
              int t, int dst, int kmax)
{
    __shared__ float Ash[BK][PAD];
    __shared__ float Bfs[BK][PAD];
    __shared__ float Bgs[BK][PAD];
    __shared__ float Bhs[BK][PAD];

    const float* __restrict__ hin  = g_hbuf[dst ^ 1];
    float* __restrict__       hout = g_hbuf[dst];

    const int tid = threadIdx.x;     // 256 threads
    const int tm  = tid >> 4;        // 0..15
    const int tn  = tid & 15;        // 0..15
    const int m0  = blockIdx.x * BM; // batch tile
    const int n0  = blockIdx.y * BN; // hidden tile

    // global-load assignment: each thread one float4 per tile
    const int lrow = tid >> 2;           // 0..63
    const int lk4  = (tid & 3) << 2;     // 0,4,8,12

    const float* xrow = x + (size_t)(m0 + lrow) * (SEQ * DIN) + (size_t)t * DIN;
    const float* hrow = hin + (size_t)(m0 + lrow) * HID;
    const float* wfr  = Wf + (size_t)(n0 + lrow) * CIN;
    const float* wgr  = Wg + (size_t)(n0 + lrow) * CIN;
    const float* whr  = Wh + (size_t)(n0 + lrow) * CIN;

    float accf[4][4], accg[4][4], acch[4][4];
#pragma unroll
    for (int i = 0; i < 4; i++)
#pragma unroll
        for (int j = 0; j < 4; j++) {
            accf[i][j] = 0.f; accg[i][j] = 0.f; acch[i][j] = 0.f;
        }

    for (int k0 = 0; k0 < kmax; k0 += BK) {
        const int k = k0 + lk4;
        // A-tile element: x-part for k<512, h-part for k>=512 (BK divides 512, no mixed chunks)
        float4 av = (k < DIN) ? *(const float4*)(xrow + k)
                              : *(const float4*)(hrow + (k - DIN));
        float4 fv = *(const float4*)(wfr + k);
        float4 gv = *(const float4*)(wgr + k);
        float4 hv = *(const float4*)(whr + k);

        __syncthreads();  // previous iteration's compute done before overwrite
        Ash[lk4 + 0][lrow] = av.x; Ash[lk4 + 1][lrow] = av.y;
        Ash[lk4 + 2][lrow] = av.z; Ash[lk4 + 3][lrow] = av.w;
        Bfs[lk4 + 0][lrow] = fv.x; Bfs[lk4 + 1][lrow] = fv.y;
        Bfs[lk4 + 2][lrow] = fv.z; Bfs[lk4 + 3][lrow] = fv.w;
        Bgs[lk4 + 0][lrow] = gv.x; Bgs[lk4 + 1][lrow] = gv.y;
        Bgs[lk4 + 2][lrow] = gv.z; Bgs[lk4 + 3][lrow] = gv.w;
        Bhs[lk4 + 0][lrow] = hv.x; Bhs[lk4 + 1][lrow] = hv.y;
        Bhs[lk4 + 2][lrow] = hv.z; Bhs[lk4 + 3][lrow] = hv.w;
        __syncthreads();

#pragma unroll
        for (int kk = 0; kk < BK; kk++) {
            float4 a4 = *(const float4*)&Ash[kk][tm << 2];
            float4 f4 = *(const float4*)&Bfs[kk][tn << 2];
            float4 g4 = *(const float4*)&Bgs[kk][tn << 2];
            float4 h4 = *(const float4*)&Bhs[kk][tn << 2];
            const float am[4] = {a4.x, a4.y, a4.z, a4.w};
            const float fn[4] = {f4.x, f4.y, f4.z, f4.w};
            const float gn[4] = {g4.x, g4.y, g4.z, g4.w};
            const float hn[4] = {h4.x, h4.y, h4.z, h4.w};
#pragma unroll
            for (int i = 0; i < 4; i++)
#pragma unroll
                for (int j = 0; j < 4; j++) {
                    accf[i][j] += am[i] * fn[j];
                    accg[i][j] += am[i] * gn[j];
                    acch[i][j] += am[i] * hn[j];
                }
        }
    }

    // epilogue: bias + gate + store h_next
#pragma unroll
    for (int i = 0; i < 4; i++) {
        const int m = m0 + (tm << 2) + i;
        float ov[4];
#pragma unroll
        for (int j = 0; j < 4; j++) {
            const int n = n0 + (tn << 2) + j;
            const float fo = accf[i][j] + bf[n];
            const float go = accg[i][j] + bg[n];
            const float ho = acch[i][j] + bh[n];
            const float gate = 1.0f / (1.0f + __expf(fo));  // sigmoid(-f)
            ov[j] = gate * go + (1.0f - gate) * ho;
        }
        float4 o4 = make_float4(ov[0], ov[1], ov[2], ov[3]);
        *(float4*)(hout + (size_t)m * HID + n0 + (tn << 2)) = o4;
    }
}

__global__ __launch_bounds__(256)
void lnn_fc(const float* __restrict__ Wfc, const float* __restrict__ bfc,
            float* __restrict__ out, int src)
{
    const int b = blockIdx.x * blockDim.x + threadIdx.x;
    if (b >= BATCH) return;
    const float* h = g_hbuf[src];
    const float4* hr = (const float4*)(h + (size_t)b * HID);
    const float4* w0 = (const float4*)(Wfc);
    const float4* w1 = (const float4*)(Wfc + HID);
    float s0 = 0.f, s1 = 0.f;
#pragma unroll 8
    for (int i = 0; i < HID / 4; i++) {
        const float4 hv = hr[i];
        const float4 a = w0[i];
        const float4 c = w1[i];
        s0 += hv.x * a.x + hv.y * a.y + hv.z * a.z + hv.w * a.w;
        s1 += hv.x * c.x + hv.y * c.y + hv.z * c.z + hv.w * c.w;
    }
    out[b * 2 + 0] = s0 + bfc[0];
    out[b * 2 + 1] = s1 + bfc[1];
}

extern "C" void kernel_launch(void* const* d_in, const int* in_sizes, int n_in,
                              void* d_out, int out_size)
{
    const float* x   = (const float*)d_in[0];
    const float* Wf  = (const float*)d_in[1];
    const float* bf  = (const float*)d_in[2];
    const float* Wg  = (const float*)d_in[3];
    const float* bg  = (const float*)d_in[4];
    const float* Wh  = (const float*)d_in[5];
    const float* bh  = (const float*)d_in[6];
    const float* Wfc = (const float*)d_in[7];
    const float* bfc = (const float*)d_in[8];
    float* out = (float*)d_out;

    dim3 grid(BATCH / BM, HID / BN);  // 32 x 16 = 512 blocks
    for (int t = 0; t < SEQ; t++) {
        // step t writes g_hbuf[t&1], reads g_hbuf[(t&1)^1]; t==0 skips the h-half (h0 == 0)
        lnn_step<<<grid, 256>>>(x, Wf, bf, Wg, bg, Wh, bh,
                                t, t & 1, (t == 0) ? DIN : CIN);
    }
    // h after t=63 lives in g_hbuf[1]
    lnn_fc<<<BATCH / 256, 256>>>(Wfc, bfc, out, 1);
}

// round 3
// speedup vs baseline: 2.3746x; 2.3746x over previous
#include <cuda_runtime.h>
#include <cuda_bf16.h>
#include <cstdint>

#define BATCH 2048
#define SEQ   64
#define DIN   512
#define HID   1024
#define CIN   1536
#define WSZ   (HID*CIN)

#define BM 128
#define BN 64          // per gate
#define BK 32
#define THREADS 256

// smem tile geometry: rows have 64B of data on an 80B pitch (conflict-free ldmatrix)
#define PITCH 80
#define A_TILE  (128*PITCH)          // 10240 B (one of hi/lo)
#define B_TILE  (64*PITCH)           // 5120 B  (one gate, one of hi/lo)
#define OFF_A   0                    // Ahi, Alo
#define OFF_B   (2*A_TILE)           // B[g][p]
#define STAGE   (2*A_TILE + 6*B_TILE)   // 51200 B
#define TILES_OFF 1024               // biases live below
#define SMEM_DYN (TILES_OFF + 2*STAGE)  // 103424 B

// ---------------- device globals ----------------
__device__ __nv_bfloat16 g_xhi[(size_t)BATCH * SEQ * DIN];
__device__ __nv_bfloat16 g_xlo[(size_t)BATCH * SEQ * DIN];
__device__ __nv_bfloat16 g_whi[3 * WSZ];
__device__ __nv_bfloat16 g_wlo[3 * WSZ];
__device__ __nv_bfloat16 g_hhi[2][BATCH * HID];
__device__ __nv_bfloat16 g_hlo[2][BATCH * HID];

// ---------------- asm helpers ----------------
__device__ __forceinline__ uint32_t smem_u32(const void* p) {
    uint32_t a;
    asm("{ .reg .u64 t; cvta.to.shared.u64 t, %1; cvt.u32.u64 %0, t; }" : "=r"(a) : "l"(p));
    return a;
}
__device__ __forceinline__ void cp16(uint32_t dst, const void* src) {
    asm volatile("cp.async.cg.shared.global [%0], [%1], 16;" :: "r"(dst), "l"(src));
}
__device__ __forceinline__ void cp_commit() {
    asm volatile("cp.async.commit_group;" ::: "memory");
}
template <int N>
__device__ __forceinline__ void cp_wait() {
    asm volatile("cp.async.wait_group %0;" :: "n"(N) : "memory");
}
__device__ __forceinline__ void ldmx4(uint32_t* r, uint32_t addr) {
    asm volatile("ldmatrix.sync.aligned.m8n8.x4.shared.b16 {%0,%1,%2,%3}, [%4];"
                 : "=r"(r[0]), "=r"(r[1]), "=r"(r[2]), "=r"(r[3]) : "r"(addr));
}
__device__ __forceinline__ void mma16816(float* c, const uint32_t* a,
                                         uint32_t b0, uint32_t b1) {
    asm volatile(
        "mma.sync.aligned.m16n8k16.row.col.f32.bf16.bf16.f32 "
        "{%0,%1,%2,%3}, {%4,%5,%6,%7}, {%8,%9}, {%0,%1,%2,%3};"
        : "+f"(c[0]), "+f"(c[1]), "+f"(c[2]), "+f"(c[3])
        : "r"(a[0]), "r"(a[1]), "r"(a[2]), "r"(a[3]), "r"(b0), "r"(b1));
}

// ---------------- split kernels (fp32 -> bf16 hi/lo) ----------------
__device__ __forceinline__ void split8(const float4 v0, const float4 v1,
                                       uint4* hi, uint4* lo) {
    float f[8] = {v0.x, v0.y, v0.z, v0.w, v1.x, v1.y, v1.z, v1.w};
    __nv_bfloat16 h[8], l[8];
#pragma unroll
    for (int i = 0; i < 8; i++) {
        h[i] = __float2bfloat16(f[i]);
        l[i] = __float2bfloat16(f[i] - __bfloat162float(h[i]));
    }
    *hi = *(const uint4*)h;
    *lo = *(const uint4*)l;
}

__global__ __launch_bounds__(256)
void split_x_kernel(const float* __restrict__ src) {
    size_t i8 = ((size_t)blockIdx.x * 256 + threadIdx.x) * 8;
    const float4* s = (const float4*)(src + i8);
    uint4 hi, lo;
    split8(s[0], s[1], &hi, &lo);
    *(uint4*)(g_xhi + i8) = hi;
    *(uint4*)(g_xlo + i8) = lo;
}

__global__ __launch_bounds__(256)
void split_w_kernel(const float* __restrict__ wf, const float* __restrict__ wg,
                    const float* __restrict__ wh) {
    size_t i8 = ((size_t)blockIdx.x * 256 + threadIdx.x) * 8;
    int gate = (int)(i8 / WSZ);
    size_t off = i8 - (size_t)gate * WSZ;
    const float* src = (gate == 0) ? wf : (gate == 1) ? wg : wh;
    const float4* s = (const float4*)(src + off);
    uint4 hi, lo;
    split8(s[0], s[1], &hi, &lo);
    *(uint4*)(g_whi + i8) = hi;
    *(uint4*)(g_wlo + i8) = lo;
}

// ---------------- step kernel ----------------
extern __shared__ char s_raw[];

__global__ __launch_bounds__(THREADS, 1)
void lnn_step(const float* __restrict__ bf, const float* __restrict__ bg,
              const float* __restrict__ bh, int t, int dst, int nchunks)
{
    const int tid  = threadIdx.x;
    const int wid  = tid >> 5;
    const int lane = tid & 31;
    const int wm   = wid & 3;      // 0..3  (M)
    const int wn   = wid >> 2;     // 0..1  (N)
    const int m0   = blockIdx.x * BM;
    const int n0   = blockIdx.y * BN;

    const __nv_bfloat16* hhi = g_hhi[dst ^ 1];
    const __nv_bfloat16* hlo = g_hlo[dst ^ 1];

    float* sb = (float*)s_raw;                      // sb[3][64]
    if (tid < 192) {
        int g = tid >> 6, j = tid & 63;
        const float* b = (g == 0) ? bf : (g == 1) ? bg : bh;
        sb[tid] = b[n0 + j];
    }

    const uint32_t tiles = smem_u32(s_raw) + TILES_OFF;

    // ---- stage fill (cp.async) ----
    auto fill = [&](int buf, int k0) {
        const uint32_t stg = tiles + buf * STAGE;
        const bool inx = (k0 < DIN);
#pragma unroll
        for (int it = 0; it < 4; it++) {            // A: 1024 x 16B
            int i = tid + it * 256;
            int p = i >> 9, r = (i >> 2) & 127, c = i & 3;
            uint32_t d = stg + OFF_A + p * A_TILE + r * PITCH + c * 16;
            const __nv_bfloat16* s;
            if (inx)
                s = (p ? g_xlo : g_xhi) + (size_t)(m0 + r) * (SEQ * DIN)
                    + (size_t)t * DIN + k0 + c * 8;
            else
                s = (p ? hlo : hhi) + (size_t)(m0 + r) * HID + (k0 - DIN) + c * 8;
            cp16(d, s);
        }
#pragma unroll
        for (int it = 0; it < 6; it++) {            // B: 1536 x 16B
            int i = tid + it * 256;
            int g = i >> 9, p = (i >> 8) & 1, r = (i >> 2) & 63, c = i & 3;
            uint32_t d = stg + OFF_B + (g * 2 + p) * B_TILE + r * PITCH + c * 16;
            const __nv_bfloat16* s = (p ? g_wlo : g_whi) + (size_t)g * WSZ
                                     + (size_t)(n0 + r) * CIN + k0 + c * 8;
            cp16(d, s);
        }
        cp_commit();
    };

    float acc[3][2][4][4];
#pragma unroll
    for (int g = 0; g < 3; g++)
#pragma unroll
        for (int mt = 0; mt < 2; mt++)
#pragma unroll
            for (int nt = 0; nt < 4; nt++)
#pragma unroll
                for (int r = 0; r < 4; r++) acc[g][mt][nt][r] = 0.f;

    // per-thread ldmatrix base offsets
    const uint32_t aoff = (uint32_t)((wm * 32 + (lane & 15)) * PITCH + (lane >> 4) * 16);
    const uint32_t boff = (uint32_t)((wn * 32 + (lane & 7) + ((lane >> 4) << 3)) * PITCH
                                     + ((lane >> 3) & 1) * 16);

    fill(0, 0);
    for (int ch = 0; ch < nchunks; ch++) {
        if (ch + 1 < nchunks) { fill((ch + 1) & 1, (ch + 1) * BK); cp_wait<1>(); }
        else                  { cp_wait<0>(); }
        __syncthreads();

        const uint32_t stg = tiles + (ch & 1) * STAGE;
#pragma unroll
        for (int k16 = 0; k16 < 2; k16++) {
            const uint32_t kb = k16 * 32;
            uint32_t ahi[2][4], alo[2][4];
#pragma unroll
            for (int mt = 0; mt < 2; mt++) {
                ldmx4(ahi[mt], stg + OFF_A + 0      + mt * (16 * PITCH) + kb + aoff);
                ldmx4(alo[mt], stg + OFF_A + A_TILE + mt * (16 * PITCH) + kb + aoff);
            }
#pragma unroll
            for (int g = 0; g < 3; g++) {
                uint32_t bhr[2][4], blr[2][4];
#pragma unroll
                for (int nt2 = 0; nt2 < 2; nt2++) {
                    uint32_t bb = stg + OFF_B + (g * 2) * B_TILE + nt2 * (16 * PITCH) + kb + boff;
                    ldmx4(bhr[nt2], bb);
                    ldmx4(blr[nt2], bb + B_TILE);
                }
#pragma unroll
                for (int mt = 0; mt < 2; mt++)
#pragma unroll
                    for (int nt = 0; nt < 4; nt++) {
                        const int n2 = nt >> 1, br = (nt & 1) * 2;
                        mma16816(acc[g][mt][nt], ahi[mt], bhr[n2][br], bhr[n2][br + 1]);
                        mma16816(acc[g][mt][nt], ahi[mt], blr[n2][br], blr[n2][br + 1]);
                        mma16816(acc[g][mt][nt], alo[mt], bhr[n2][br], bhr[n2][br + 1]);
                    }
            }
        }
        __syncthreads();
    }

    // ---- epilogue: bias + sigmoid gate, write h hi/lo ----
    __nv_bfloat16* ohi = g_hhi[dst];
    __nv_bfloat16* olo = g_hlo[dst];
#pragma unroll
    for (int mt = 0; mt < 2; mt++)
#pragma unroll
        for (int nt = 0; nt < 4; nt++)
#pragma unroll
            for (int rh = 0; rh < 2; rh++) {
                const int row  = m0 + wm * 32 + mt * 16 + (lane >> 2) + rh * 8;
                const int colb = wn * 32 + nt * 8 + (lane & 3) * 2;   // block-local
                float v[2], vl[2];
#pragma unroll
                for (int q = 0; q < 2; q++) {
                    const float fo = acc[0][mt][nt][2 * rh + q] + sb[colb + q];
                    const float go = acc[1][mt][nt][2 * rh + q] + sb[64 + colb + q];
                    const float ho = acc[2][mt][nt][2 * rh + q] + sb[128 + colb + q];
                    const float gate = 1.0f / (1.0f + __expf(fo));    // sigmoid(-f)
                    const float val = gate * go + (1.0f - gate) * ho;
                    const __nv_bfloat16 hi = __float2bfloat16(val);
                    v[q]  = __bfloat162float(hi);
                    vl[q] = val - v[q];
                }
                const size_t o = (size_t)row * HID + n0 + colb;
                __nv_bfloat162 phi, plo;
                phi.x = __float2bfloat16(v[0]);  phi.y = __float2bfloat16(v[1]);
                plo.x = __float2bfloat16(vl[0]); plo.y = __float2bfloat16(vl[1]);
                *(__nv_bfloat162*)(ohi + o) = phi;
                *(__nv_bfloat162*)(olo + o) = plo;
            }
}

// ---------------- FC head ----------------
__global__ __launch_bounds__(256)
void lnn_fc(const float* __restrict__ Wfc, const float* __restrict__ bfc,
            float* __restrict__ out, int src)
{
    const int b = blockIdx.x * blockDim.x + threadIdx.x;
    if (b >= BATCH) return;
    const __nv_bfloat16* hh = g_hhi[src] + (size_t)b * HID;
    const __nv_bfloat16* hl = g_hlo[src] + (size_t)b * HID;
    const float* w0 = Wfc;
    const float* w1 = Wfc + HID;
    float s0 = 0.f, s1 = 0.f;
#pragma unroll 8
    for (int i = 0; i < HID; i++) {
        float h = __bfloat162float(hh[i]) + __bfloat162float(hl[i]);
        s0 += h * w0[i];
        s1 += h * w1[i];
    }
    out[b * 2 + 0] = s0 + bfc[0];
    out[b * 2 + 1] = s1 + bfc[1];
}

// ---------------- launch ----------------
extern "C" void kernel_launch(void* const* d_in, const int* in_sizes, int n_in,
                              void* d_out, int out_size)
{
    const float* x   = (const float*)d_in[0];
    const float* Wf  = (const float*)d_in[1];
    const float* bf  = (const float*)d_in[2];
    const float* Wg  = (const float*)d_in[3];
    const float* bg  = (const float*)d_in[4];
    const float* Wh  = (const float*)d_in[5];
    const float* bh  = (const float*)d_in[6];
    const float* Wfc = (const float*)d_in[7];
    const float* bfc = (const float*)d_in[8];
    float* out = (float*)d_out;

    cudaFuncSetAttribute(lnn_step, cudaFuncAttributeMaxDynamicSharedMemorySize, SMEM_DYN);

    split_x_kernel<<<(BATCH * SEQ * DIN) / 2048, 256>>>(x);
    split_w_kernel<<<(3 * WSZ) / 2048, 256>>>(Wf, Wg, Wh);

    dim3 grid(BATCH / BM, HID / BN);   // 16 x 16 = 256 CTAs
    for (int t = 0; t < SEQ; t++) {
        lnn_step<<<grid, THREADS, SMEM_DYN>>>(bf, bg, bh, t, t & 1,
                                              (t == 0) ? (DIN / BK) : (CIN / BK));
    }
    lnn_fc<<<BATCH / 256, 256>>>(Wfc, bfc, out, 1);
}

// round 4
// speedup vs baseline: 2.3887x; 1.0059x over previous
#include <cuda_runtime.h>
#include <cuda_bf16.h>
#include <cstdint>

#define BATCH 2048
#define SEQ   64
#define DIN   512
#define HID   1024
#define CIN   1536
#define WSZ   (HID*CIN)

#define BM 128
#define BN 64          // per gate
#define BK 32
#define THREADS 256

// smem tile geometry: rows have 64B of data on an 80B pitch (conflict-free ldmatrix)
#define PITCH 80
#define A_TILE  (128*PITCH)          // 10240 B (one of hi/lo)
#define B_TILE  (64*PITCH)           // 5120 B  (one gate, one of hi/lo)
#define OFF_A   0                    // Ahi, Alo
#define OFF_B   (2*A_TILE)           // B[g][p]
#define STAGE   (2*A_TILE + 6*B_TILE)   // 51200 B
#define TILES_OFF 1024               // biases live below
#define SMEM_DYN (TILES_OFF + 2*STAGE)  // 103424 B

// ---------------- device globals ----------------
__device__ __nv_bfloat16 g_xhi[(size_t)BATCH * SEQ * DIN];
__device__ __nv_bfloat16 g_xlo[(size_t)BATCH * SEQ * DIN];
__device__ __nv_bfloat16 g_whi[3 * WSZ];
__device__ __nv_bfloat16 g_wlo[3 * WSZ];
__device__ __nv_bfloat16 g_hhi[2][BATCH * HID];
__device__ __nv_bfloat16 g_hlo[2][BATCH * HID];

// ---------------- asm helpers ----------------
__device__ __forceinline__ uint32_t smem_u32(const void* p) {
    uint32_t a;
    asm("{ .reg .u64 t; cvta.to.shared.u64 t, %1; cvt.u32.u64 %0, t; }" : "=r"(a) : "l"(p));
    return a;
}
__device__ __forceinline__ void cp16(uint32_t dst, const void* src) {
    asm volatile("cp.async.cg.shared.global [%0], [%1], 16;" :: "r"(dst), "l"(src));
}
__device__ __forceinline__ void cp_commit() {
    asm volatile("cp.async.commit_group;" ::: "memory");
}
template <int N>
__device__ __forceinline__ void cp_wait() {
    asm volatile("cp.async.wait_group %0;" :: "n"(N) : "memory");
}
__device__ __forceinline__ void ldmx4(uint32_t* r, uint32_t addr) {
    asm volatile("ldmatrix.sync.aligned.m8n8.x4.shared.b16 {%0,%1,%2,%3}, [%4];"
                 : "=r"(r[0]), "=r"(r[1]), "=r"(r[2]), "=r"(r[3]) : "r"(addr));
}
__device__ __forceinline__ void mma16816(float* c, const uint32_t* a,
                                         uint32_t b0, uint32_t b1) {
    asm volatile(
        "mma.sync.aligned.m16n8k16.row.col.f32.bf16.bf16.f32 "
        "{%0,%1,%2,%3}, {%4,%5,%6,%7}, {%8,%9}, {%0,%1,%2,%3};"
        : "+f"(c[0]), "+f"(c[1]), "+f"(c[2]), "+f"(c[3])
        : "r"(a[0]), "r"(a[1]), "r"(a[2]), "r"(a[3]), "r"(b0), "r"(b1));
}

// ---------------- split kernels (fp32 -> bf16 hi/lo) ----------------
__device__ __forceinline__ void split8(const float4 v0, const float4 v1,
                                       uint4* hi, uint4* lo) {
    float f[8] = {v0.x, v0.y, v0.z, v0.w, v1.x, v1.y, v1.z, v1.w};
    __nv_bfloat16 h[8], l[8];
#pragma unroll
    for (int i = 0; i < 8; i++) {
        h[i] = __float2bfloat16(f[i]);
        l[i] = __float2bfloat16(f[i] - __bfloat162float(h[i]));
    }
    *hi = *(const uint4*)h;
    *lo = *(const uint4*)l;
}

__global__ __launch_bounds__(256)
void split_x_kernel(const float* __restrict__ src) {
    size_t i8 = ((size_t)blockIdx.x * 256 + threadIdx.x) * 8;
    const float4* s = (const float4*)(src + i8);
    uint4 hi, lo;
    split8(s[0], s[1], &hi, &lo);
    *(uint4*)(g_xhi + i8) = hi;
    *(uint4*)(g_xlo + i8) = lo;
}

__global__ __launch_bounds__(256)
void split_w_kernel(const float* __restrict__ wf, const float* __restrict__ wg,
                    const float* __restrict__ wh) {
    size_t i8 = ((size_t)blockIdx.x * 256 + threadIdx.x) * 8;
    int gate = (int)(i8 / WSZ);
    size_t off = i8 - (size_t)gate * WSZ;
    const float* src = (gate == 0) ? wf : (gate == 1) ? wg : wh;
    const float4* s = (const float4*)(src + off);
    uint4 hi, lo;
    split8(s[0], s[1], &hi, &lo);
    *(uint4*)(g_whi + i8) = hi;
    *(uint4*)(g_wlo + i8) = lo;
}

// ---------------- step kernel ----------------
extern __shared__ char s_raw[];

__global__ __launch_bounds__(THREADS, 1)
void lnn_step(const float* __restrict__ bf, const float* __restrict__ bg,
              const float* __restrict__ bh, int t, int dst, int nchunks)
{
    const int tid  = threadIdx.x;
    const int wid  = tid >> 5;
    const int lane = tid & 31;
    const int wm   = wid & 3;      // 0..3  (M)
    const int wn   = wid >> 2;     // 0..1  (N)
    const int m0   = blockIdx.x * BM;
    const int n0   = blockIdx.y * BN;

    const __nv_bfloat16* hhi = g_hhi[dst ^ 1];
    const __nv_bfloat16* hlo = g_hlo[dst ^ 1];

    float* sb = (float*)s_raw;                      // sb[3][64]
    if (tid < 192) {
        int g = tid >> 6, j = tid & 63;
        const float* b = (g == 0) ? bf : (g == 1) ? bg : bh;
        sb[tid] = b[n0 + j];
    }

    const uint32_t tiles = smem_u32(s_raw) + TILES_OFF;

    // ---- stage fill (cp.async) ----
    auto fill = [&](int buf, int k0) {
        const uint32_t stg = tiles + buf * STAGE;
        const bool inx = (k0 < DIN);
#pragma unroll
        for (int it = 0; it < 4; it++) {            // A: 1024 x 16B
            int i = tid + it * 256;
            int p = i >> 9, r = (i >> 2) & 127, c = i & 3;
            uint32_t d = stg + OFF_A + p * A_TILE + r * PITCH + c * 16;
            const __nv_bfloat16* s;
            if (inx)
                s = (p ? g_xlo : g_xhi) + (size_t)(m0 + r) * (SEQ * DIN)
                    + (size_t)t * DIN + k0 + c * 8;
            else
                s = (p ? hlo : hhi) + (size_t)(m0 + r) * HID + (k0 - DIN) + c * 8;
            cp16(d, s);
        }
#pragma unroll
        for (int it = 0; it < 6; it++) {            // B: 1536 x 16B
            int i = tid + it * 256;
            int g = i >> 9, p = (i >> 8) & 1, r = (i >> 2) & 63, c = i & 3;
            uint32_t d = stg + OFF_B + (g * 2 + p) * B_TILE + r * PITCH + c * 16;
            const __nv_bfloat16* s = (p ? g_wlo : g_whi) + (size_t)g * WSZ
                                     + (size_t)(n0 + r) * CIN + k0 + c * 8;
            cp16(d, s);
        }
        cp_commit();
    };

    float acc[3][2][4][4];
#pragma unroll
    for (int g = 0; g < 3; g++)
#pragma unroll
        for (int mt = 0; mt < 2; mt++)
#pragma unroll
            for (int nt = 0; nt < 4; nt++)
#pragma unroll
                for (int r = 0; r < 4; r++) acc[g][mt][nt][r] = 0.f;

    // per-thread ldmatrix base offsets
    const uint32_t aoff = (uint32_t)((wm * 32 + (lane & 15)) * PITCH + (lane >> 4) * 16);
    const uint32_t boff = (uint32_t)((wn * 32 + (lane & 7) + ((lane >> 4) << 3)) * PITCH
                                     + ((lane >> 3) & 1) * 16);

    fill(0, 0);
    for (int ch = 0; ch < nchunks; ch++) {
        if (ch + 1 < nchunks) { fill((ch + 1) & 1, (ch + 1) * BK); cp_wait<1>(); }
        else                  { cp_wait<0>(); }
        __syncthreads();

        const uint32_t stg = tiles + (ch & 1) * STAGE;
#pragma unroll
        for (int k16 = 0; k16 < 2; k16++) {
            const uint32_t kb = k16 * 32;

            // ---- load ALL fragments for this k16 first ----
            uint32_t ahi[2][4], alo[2][4];
#pragma unroll
            for (int mt = 0; mt < 2; mt++) {
                ldmx4(ahi[mt], stg + OFF_A + 0      + mt * (16 * PITCH) + kb + aoff);
                ldmx4(alo[mt], stg + OFF_A + A_TILE + mt * (16 * PITCH) + kb + aoff);
            }
            uint32_t bhr[3][2][4], blr[3][2][4];
#pragma unroll
            for (int g = 0; g < 3; g++)
#pragma unroll
                for (int nt2 = 0; nt2 < 2; nt2++) {
                    uint32_t bb = stg + OFF_B + (g * 2) * B_TILE + nt2 * (16 * PITCH) + kb + boff;
                    ldmx4(bhr[g][nt2], bb);
                    ldmx4(blr[g][nt2], bb + B_TILE);
                }

            // ---- 3 passes by split-product: 24 independent MMAs per pass ----
            // pass 0: Ahi * Bhi
#pragma unroll
            for (int g = 0; g < 3; g++)
#pragma unroll
                for (int mt = 0; mt < 2; mt++)
#pragma unroll
                    for (int nt = 0; nt < 4; nt++) {
                        const int n2 = nt >> 1, br = (nt & 1) * 2;
                        mma16816(acc[g][mt][nt], ahi[mt], bhr[g][n2][br], bhr[g][n2][br + 1]);
                    }
            // pass 1: Ahi * Blo
#pragma unroll
            for (int g = 0; g < 3; g++)
#pragma unroll
                for (int mt = 0; mt < 2; mt++)
#pragma unroll
                    for (int nt = 0; nt < 4; nt++) {
                        const int n2 = nt >> 1, br = (nt & 1) * 2;
                        mma16816(acc[g][mt][nt], ahi[mt], blr[g][n2][br], blr[g][n2][br + 1]);
                    }
            // pass 2: Alo * Bhi
#pragma unroll
            for (int g = 0; g < 3; g++)
#pragma unroll
                for (int mt = 0; mt < 2; mt++)
#pragma unroll
                    for (int nt = 0; nt < 4; nt++) {
                        const int n2 = nt >> 1, br = (nt & 1) * 2;
                        mma16816(acc[g][mt][nt], alo[mt], bhr[g][n2][br], bhr[g][n2][br + 1]);
                    }
        }
        __syncthreads();
    }

    // ---- epilogue: bias + sigmoid gate, write h hi/lo ----
    __nv_bfloat16* ohi = g_hhi[dst];
    __nv_bfloat16* olo = g_hlo[dst];
#pragma unroll
    for (int mt = 0; mt < 2; mt++)
#pragma unroll
        for (int nt = 0; nt < 4; nt++)
#pragma unroll
            for (int rh = 0; rh < 2; rh++) {
                const int row  = m0 + wm * 32 + mt * 16 + (lane >> 2) + rh * 8;
                const int colb = wn * 32 + nt * 8 + (lane & 3) * 2;   // block-local
                float v[2], vl[2];
#pragma unroll
                for (int q = 0; q < 2; q++) {
                    const float fo = acc[0][mt][nt][2 * rh + q] + sb[colb + q];
                    const float go = acc[1][mt][nt][2 * rh + q] + sb[64 + colb + q];
                    const float ho = acc[2][mt][nt][2 * rh + q] + sb[128 + colb + q];
                    const float gate = 1.0f / (1.0f + __expf(fo));    // sigmoid(-f)
                    const float val = gate * go + (1.0f - gate) * ho;
                    const __nv_bfloat16 hi = __float2bfloat16(val);
                    v[q]  = __bfloat162float(hi);
                    vl[q] = val - v[q];
                }
                const size_t o = (size_t)row * HID + n0 + colb;
                __nv_bfloat162 phi, plo;
                phi.x = __float2bfloat16(v[0]);  phi.y = __float2bfloat16(v[1]);
                plo.x = __float2bfloat16(vl[0]); plo.y = __float2bfloat16(vl[1]);
                *(__nv_bfloat162*)(ohi + o) = phi;
                *(__nv_bfloat162*)(olo + o) = plo;
            }
}

// ---------------- FC head ----------------
__global__ __launch_bounds__(256)
void lnn_fc(const float* __restrict__ Wfc, const float* __restrict__ bfc,
            float* __restrict__ out, int src)
{
    const int b = blockIdx.x * blockDim.x + threadIdx.x;
    if (b >= BATCH) return;
    const __nv_bfloat16* hh = g_hhi[src] + (size_t)b * HID;
    const __nv_bfloat16* hl = g_hlo[src] + (size_t)b * HID;
    const float* w0 = Wfc;
    const float* w1 = Wfc + HID;
    float s0 = 0.f, s1 = 0.f;
#pragma unroll 8
    for (int i = 0; i < HID; i++) {
        float h = __bfloat162float(hh[i]) + __bfloat162float(hl[i]);
        s0 += h * w0[i];
        s1 += h * w1[i];
    }
    out[b * 2 + 0] = s0 + bfc[0];
    out[b * 2 + 1] = s1 + bfc[1];
}

// ---------------- launch ----------------
extern "C" void kernel_launch(void* const* d_in, const int* in_sizes, int n_in,
                              void* d_out, int out_size)
{
    const float* x   = (const float*)d_in[0];
    const float* Wf  = (const float*)d_in[1];
    const float* bf  = (const float*)d_in[2];
    const float* Wg  = (const float*)d_in[3];
    const float* bg  = (const float*)d_in[4];
    const float* Wh  = (const float*)d_in[5];
    const float* bh  = (const float*)d_in[6];
    const float* Wfc = (const float*)d_in[7];
    const float* bfc = (const float*)d_in[8];
    float* out = (float*)d_out;

    cudaFuncSetAttribute(lnn_step, cudaFuncAttributeMaxDynamicSharedMemorySize, SMEM_DYN);

    split_x_kernel<<<(BATCH * SEQ * DIN) / 2048, 256>>>(x);
    split_w_kernel<<<(3 * WSZ) / 2048, 256>>>(Wf, Wg, Wh);

    dim3 grid(BATCH / BM, HID / BN);   // 16 x 16 = 256 CTAs
    for (int t = 0; t < SEQ; t++) {
        lnn_step<<<grid, THREADS, SMEM_DYN>>>(bf, bg, bh, t, t & 1,
                                              (t == 0) ? (DIN / BK) : (CIN / BK));
    }
    lnn_fc<<<BATCH / 256, 256>>>(Wfc, bfc, out, 1);
}